// round 1
// baseline (speedup 1.0000x reference)
#include <cuda_runtime.h>
#include <math.h>

// ---------------- problem constants ----------------
#define N_TOT   100000
#define N_SEL   5000        // 5 blocks * 1000
#define NB      5
#define BATCH   1000
#define DIMS    256
#define NBUCK   65536       // 16-bit MSB buckets for stable sort
#define PARTITIONABLE 1     // jax_threefry_partitionable default (>=0.4.36). Flip to 0 if rel_err is large.

// ---------------- scratch (static device globals; no allocations) ----------------
__device__ unsigned g_key[N_TOT];
__device__ unsigned g_keyB[N_TOT], g_valB[N_TOT], g_idxB[N_TOT];
__device__ unsigned g_keyC[N_TOT], g_valC[N_TOT], g_idxC[N_TOT];
__device__ unsigned g_cnt[NBUCK], g_start[NBUCK], g_cur[NBUCK];
__device__ float    g_X[(size_t)N_SEL * DIMS];
__device__ float    g_sq[N_SEL];
__device__ int      g_lab[N_SEL];
__device__ unsigned g_ap[N_SEL], g_an[N_SEL];   // float bits; dist >= 0 so unsigned order == float order

// ---------------- threefry-2x32-20 (exact JAX algorithm) ----------------
__device__ __forceinline__ void tf2x32(unsigned k0, unsigned k1, unsigned x0, unsigned x1,
                                       unsigned &o0, unsigned &o1) {
    unsigned ks2 = k0 ^ k1 ^ 0x1BD11BDAu;
    x0 += k0; x1 += k1;
#define TFR(r) { x0 += x1; x1 = (x1 << (r)) | (x1 >> (32 - (r))); x1 ^= x0; }
    TFR(13) TFR(15) TFR(26) TFR(6)   x0 += k1;  x1 += ks2 + 1u;
    TFR(17) TFR(29) TFR(16) TFR(24)  x0 += ks2; x1 += k0  + 2u;
    TFR(13) TFR(15) TFR(26) TFR(6)   x0 += k0;  x1 += k1  + 3u;
    TFR(17) TFR(29) TFR(16) TFR(24)  x0 += k1;  x1 += ks2 + 4u;
    TFR(13) TFR(15) TFR(26) TFR(6)   x0 += ks2; x1 += k0  + 5u;
#undef TFR
    o0 = x0; o1 = x1;
}

// subkey for shuffle round `round` (0 or 1), starting from key = (0, uu)
__device__ __forceinline__ void get_subkey(unsigned uu, int round, unsigned &s0, unsigned &s1) {
    unsigned K0 = 0u, K1 = uu;
#if PARTITIONABLE
    // fold-like split: subkey = TF(key,0,1); new key = TF(key,0,0)
    for (int j = 0;; j++) {
        tf2x32(K0, K1, 0u, 1u, s0, s1);
        if (j == round) break;
        unsigned n0, n1; tf2x32(K0, K1, 0u, 0u, n0, n1);
        K0 = n0; K1 = n1;
    }
#else
    // original split: counts [0,1,2,3] -> pairs (0,2),(1,3); key=(o0a,o0b), sub=(o1a,o1b)
    for (int j = 0;; j++) {
        unsigned a0, a1, b0, b1;
        tf2x32(K0, K1, 0u, 2u, a0, a1);
        tf2x32(K0, K1, 1u, 3u, b0, b1);
        s0 = a1; s1 = b1;
        if (j == round) break;
        K0 = a0; K1 = b0;
    }
#endif
}

// ---------------- kernels ----------------
__global__ void k_init_all() {
    int i = blockIdx.x * blockDim.x + threadIdx.x;
    if (i < NBUCK) g_cnt[i] = 0u;
    if (i < N_SEL) { g_ap[i] = 0u; g_an[i] = 0x7f800000u; }  // 0.0f / +inf
}

__global__ void k_zero_cnt() {
    int i = blockIdx.x * blockDim.x + threadIdx.x;
    if (i < NBUCK) g_cnt[i] = 0u;
}

__global__ void k_keys(const int* uuP, int round) {
    int i = blockIdx.x * blockDim.x + threadIdx.x;
    unsigned uu = (unsigned)uuP[0];
#if PARTITIONABLE
    if (i >= N_TOT) return;
    unsigned s0, s1; get_subkey(uu, round, s0, s1);
    unsigned o0, o1; tf2x32(s0, s1, 0u, (unsigned)i, o0, o1);
    g_key[i] = o0;                      // bits1 for 32-bit width
#else
    if (i >= N_TOT / 2) return;
    unsigned s0, s1; get_subkey(uu, round, s0, s1);
    unsigned o0, o1; tf2x32(s0, s1, (unsigned)i, (unsigned)(i + N_TOT / 2), o0, o1);
    g_key[i] = o0; g_key[i + N_TOT / 2] = o1;
#endif
}

__global__ void k_hist() {
    int i = blockIdx.x * blockDim.x + threadIdx.x;
    if (i < N_TOT) atomicAdd(&g_cnt[g_key[i] >> 16], 1u);
}

// exclusive scan over 65536 counters; 1 block of 1024 threads, 64 buckets/thread
__global__ void k_scan() {
    __shared__ unsigned s[1024];
    int t = threadIdx.x;
    unsigned base = t * 64u;
    unsigned sum = 0u;
    for (int j = 0; j < 64; j++) sum += g_cnt[base + j];
    s[t] = sum;
    __syncthreads();
    for (int off = 1; off < 1024; off <<= 1) {
        unsigned v = (t >= off) ? s[t - off] : 0u;
        __syncthreads();
        s[t] += v;
        __syncthreads();
    }
    unsigned run = s[t] - sum;          // exclusive prefix of this thread's chunk
    for (int j = 0; j < 64; j++) {
        unsigned c = g_cnt[base + j];
        g_start[base + j] = run;
        g_cur[base + j]   = run;
        run += c;
    }
}

__global__ void k_scatter(int round) {
    int i = blockIdx.x * blockDim.x + threadIdx.x;
    if (i >= N_TOT) return;
    unsigned k = g_key[i];
    unsigned p = atomicAdd(&g_cur[k >> 16], 1u);
    if (round == 0) { g_keyB[p] = k; g_valB[p] = (unsigned)i;  g_idxB[p] = (unsigned)i; }
    else            { g_keyC[p] = k; g_valC[p] = g_valB[i];    g_idxC[p] = (unsigned)i; }
}

// restore exact stable order within each bucket: sort by (full key, original index)
__global__ void k_bsort(int round) {
    int b = blockIdx.x * blockDim.x + threadIdx.x;
    if (b >= NBUCK) return;
    unsigned n = g_cnt[b];
    if (n < 2u) return;
    unsigned s = g_start[b];
    unsigned* key = round ? g_keyC : g_keyB;
    unsigned* val = round ? g_valC : g_valB;
    unsigned* idx = round ? g_idxC : g_idxB;
    for (unsigned a = s + 1u; a < s + n; a++) {
        unsigned k = key[a], v = val[a], x = idx[a];
        int c = (int)a - 1;
        while (c >= (int)s && (key[c] > k || (key[c] == k && idx[c] > x))) {
            key[c + 1] = key[c]; val[c + 1] = val[c]; idx[c + 1] = idx[c];
            c--;
        }
        key[c + 1] = k; val[c + 1] = v; idx[c + 1] = x;
    }
}

// gather the first 5000 permuted rows + per-row squared norm + label
__global__ void k_gather(const float* __restrict__ X, const int* __restrict__ T) {
    int row = blockIdx.x;          // 0..4999
    int t = threadIdx.x;           // 64 threads, one float4 each
    unsigned src = g_valC[row];
    float4 v = ((const float4*)(X + (size_t)src * DIMS))[t];
    ((float4*)(g_X + (size_t)row * DIMS))[t] = v;
    float ss = v.x * v.x + v.y * v.y + v.z * v.z + v.w * v.w;
    __shared__ float red[64];
    red[t] = ss;
    __syncthreads();
    if (t < 32) {
        float x = red[t] + red[t + 32];
        for (int o = 16; o > 0; o >>= 1) x += __shfl_down_sync(0xffffffffu, x, o);
        if (t == 0) { g_sq[row] = x; g_lab[row] = T[src]; }
    }
}

// fused  G = Xb*Xb^T  +  dist  +  batch-hard mining
// grid: (16 row-tiles of 64, 2 column halves of 500, 5 blocks); 256 threads; 4x4 microtile
__global__ void k_main() {
    extern __shared__ float sm[];
    float* As  = sm;                 // [256][64] k-major
    float* Bs  = sm + 256 * 64;      // [256][64] k-major
    float* sqA = sm + 2 * 256 * 64;  // [64]
    float* sqB = sqA + 64;           // [64]
    int*   labA = (int*)(sqB + 64);  // [64]
    int*   labB = labA + 64;         // [64]

    const int tid = threadIdx.x;
    const int tx = tid & 15, ty = tid >> 4;
    const int blk = blockIdx.z;
    const int r0 = blockIdx.x * 64;
    const int cStart = blockIdx.y * 500;
    const int cEnd = cStart + 500;
    const int nrows = min(64, BATCH - r0);
    const int rowBase = blk * BATCH + r0;

    // load A tile (k-major; zero-pad invalid rows)
    for (int idx = tid; idx < 64 * 64; idx += 256) {
        int r = idx & 63, q = idx >> 6;
        float4 v = make_float4(0.f, 0.f, 0.f, 0.f);
        if (r < nrows) v = *(const float4*)&g_X[(size_t)(rowBase + r) * DIMS + q * 4];
        As[(q * 4 + 0) * 64 + r] = v.x;
        As[(q * 4 + 1) * 64 + r] = v.y;
        As[(q * 4 + 2) * 64 + r] = v.z;
        As[(q * 4 + 3) * 64 + r] = v.w;
    }
    if (tid < 64) {
        sqA[tid]  = (tid < nrows) ? g_sq[rowBase + tid] : 0.f;
        labA[tid] = (tid < nrows) ? g_lab[rowBase + tid] : -1;
    }

    float rmax[4] = {0.f, 0.f, 0.f, 0.f};
    float rmin[4];
    rmin[0] = rmin[1] = rmin[2] = rmin[3] = __uint_as_float(0x7f800000u);

    for (int c0 = cStart; c0 < cEnd; c0 += 64) {
        const int ncols = min(64, cEnd - c0);
        const int colBase = blk * BATCH + c0;
        __syncthreads();   // Bs reuse vs previous epilogue; also fences the A load on iter 0
        for (int idx = tid; idx < 64 * 64; idx += 256) {
            int r = idx & 63, q = idx >> 6;
            float4 v = make_float4(0.f, 0.f, 0.f, 0.f);
            if (r < ncols) v = *(const float4*)&g_X[(size_t)(colBase + r) * DIMS + q * 4];
            Bs[(q * 4 + 0) * 64 + r] = v.x;
            Bs[(q * 4 + 1) * 64 + r] = v.y;
            Bs[(q * 4 + 2) * 64 + r] = v.z;
            Bs[(q * 4 + 3) * 64 + r] = v.w;
        }
        if (tid < 64) {
            sqB[tid]  = (tid < ncols) ? g_sq[colBase + tid] : 0.f;
            labB[tid] = (tid < ncols) ? g_lab[colBase + tid] : 0x7fffffff;
        }
        __syncthreads();

        float acc[4][4];
#pragma unroll
        for (int i = 0; i < 4; i++)
#pragma unroll
            for (int j = 0; j < 4; j++) acc[i][j] = 0.f;

#pragma unroll 8
        for (int k = 0; k < DIMS; k++) {
            float4 a = *(const float4*)&As[k * 64 + ty * 4];
            float4 b = *(const float4*)&Bs[k * 64 + tx * 4];
            acc[0][0] += a.x * b.x; acc[0][1] += a.x * b.y; acc[0][2] += a.x * b.z; acc[0][3] += a.x * b.w;
            acc[1][0] += a.y * b.x; acc[1][1] += a.y * b.y; acc[1][2] += a.y * b.z; acc[1][3] += a.y * b.w;
            acc[2][0] += a.z * b.x; acc[2][1] += a.z * b.y; acc[2][2] += a.z * b.z; acc[2][3] += a.z * b.w;
            acc[3][0] += a.w * b.x; acc[3][1] += a.w * b.y; acc[3][2] += a.w * b.z; acc[3][3] += a.w * b.w;
        }

        // epilogue: distances + batch-hard update
#pragma unroll
        for (int i = 0; i < 4; i++) {
            int gr = ty * 4 + i;
            float sqi = sqA[gr];
            int   li  = labA[gr];
#pragma unroll
            for (int j = 0; j < 4; j++) {
                int gc = tx * 4 + j;
                if (gr < nrows && gc < ncols) {
                    float d2 = sqi + sqB[gc] - 2.f * acc[i][j];
                    float dist = sqrtf(fmaxf(d2, 1e-12f));
                    if (li == labB[gc]) rmax[i] = fmaxf(rmax[i], dist);
                    else                rmin[i] = fminf(rmin[i], dist);
                }
            }
        }
    }

    // merge per-thread partials into global row max/min (monotone bit tricks; dist >= 0)
#pragma unroll
    for (int i = 0; i < 4; i++) {
        int gr = ty * 4 + i;
        if (gr < nrows) {
            int row = rowBase + gr;
            atomicMax(&g_ap[row], __float_as_uint(rmax[i]));
            atomicMin(&g_an[row], __float_as_uint(rmin[i]));
        }
    }
}

// deterministic final reduction:  sum_b mean_b relu(ap - an + 0.5)  ==  (sum of all row losses)/1000
__global__ void k_reduce(float* __restrict__ out) {
    __shared__ float s[1024];
    int t = threadIdx.x;
    float acc = 0.f;
    for (int i = t; i < N_SEL; i += 1024) {
        float ap = __uint_as_float(g_ap[i]);
        float an = __uint_as_float(g_an[i]);   // +inf if no negative -> loss 0
        acc += fmaxf(ap - an + 0.5f, 0.f);
    }
    s[t] = acc;
    __syncthreads();
    for (int off = 512; off > 0; off >>= 1) {
        if (t < off) s[t] += s[t + off];
        __syncthreads();
    }
    if (t == 0) out[0] = s[0] * (1.0f / (float)BATCH);
}

// ---------------- launch ----------------
extern "C" void kernel_launch(void* const* d_in, const int* in_sizes, int n_in,
                              void* d_out, int out_size) {
    const float* X  = (const float*)d_in[0];
    const int*   T  = (const int*)d_in[1];
    const int*   UU = (const int*)d_in[2];
    float* out = (float*)d_out;
    (void)in_sizes; (void)n_in; (void)out_size;

    const int TB = 256;
    const int gN = (N_TOT + TB - 1) / TB;
    const int gB = NBUCK / TB;
    const int SMEM_MAIN = (2 * 256 * 64 + 2 * 64) * (int)sizeof(float) + 2 * 64 * (int)sizeof(int);

    cudaFuncSetAttribute(k_main, cudaFuncAttributeMaxDynamicSharedMemorySize, SMEM_MAIN);

    k_init_all<<<gB, TB>>>();

    // shuffle round 1
    k_keys<<<gN, TB>>>(UU, 0);
    k_hist<<<gN, TB>>>();
    k_scan<<<1, 1024>>>();
    k_scatter<<<gN, TB>>>(0);
    k_bsort<<<gB, TB>>>(0);

    // shuffle round 2
    k_zero_cnt<<<gB, TB>>>();
    k_keys<<<gN, TB>>>(UU, 1);
    k_hist<<<gN, TB>>>();
    k_scan<<<1, 1024>>>();
    k_scatter<<<gN, TB>>>(1);
    k_bsort<<<gB, TB>>>(1);

    // gather + fused gemm/mining + reduce
    k_gather<<<N_SEL, 64>>>(X, T);
    k_main<<<dim3(16, 2, NB), 256, SMEM_MAIN>>>();
    k_reduce<<<1, 1024>>>(out);
}

// round 2
// speedup vs baseline: 2.1556x; 2.1556x over previous
#include <cuda_runtime.h>
#include <math.h>

// ---------------- problem constants ----------------
#define N_TOT   100000
#define N_SEL   5000        // 5 blocks * 1000
#define NB      5
#define BATCH   1000
#define DIMS    256
#define NBUCK   65536       // 16-bit MSB buckets for stable sort
#define PARTITIONABLE 1

// ---------------- scratch (static device globals; no allocations) ----------------
__device__ unsigned g_key[N_TOT];
__device__ unsigned g_keyB[N_TOT], g_valB[N_TOT], g_idxB[N_TOT];
__device__ unsigned g_keyC[N_TOT], g_valC[N_TOT], g_idxC[N_TOT];
__device__ unsigned g_cnt[NBUCK], g_start[NBUCK], g_cur[NBUCK];
__device__ unsigned g_bsum[64];
__device__ float    g_X[(size_t)N_SEL * DIMS];
__device__ float    g_sq[N_SEL];
__device__ int      g_lab[N_SEL];
__device__ unsigned g_ap[N_SEL], g_an[N_SEL];   // float bits; dist >= 0 so unsigned order == float order

// ---------------- threefry-2x32-20 (exact JAX algorithm) ----------------
__device__ __forceinline__ void tf2x32(unsigned k0, unsigned k1, unsigned x0, unsigned x1,
                                       unsigned &o0, unsigned &o1) {
    unsigned ks2 = k0 ^ k1 ^ 0x1BD11BDAu;
    x0 += k0; x1 += k1;
#define TFR(r) { x0 += x1; x1 = (x1 << (r)) | (x1 >> (32 - (r))); x1 ^= x0; }
    TFR(13) TFR(15) TFR(26) TFR(6)   x0 += k1;  x1 += ks2 + 1u;
    TFR(17) TFR(29) TFR(16) TFR(24)  x0 += ks2; x1 += k0  + 2u;
    TFR(13) TFR(15) TFR(26) TFR(6)   x0 += k0;  x1 += k1  + 3u;
    TFR(17) TFR(29) TFR(16) TFR(24)  x0 += k1;  x1 += ks2 + 4u;
    TFR(13) TFR(15) TFR(26) TFR(6)   x0 += ks2; x1 += k0  + 5u;
#undef TFR
    o0 = x0; o1 = x1;
}

__device__ __forceinline__ void get_subkey(unsigned uu, int round, unsigned &s0, unsigned &s1) {
    unsigned K0 = 0u, K1 = uu;
#if PARTITIONABLE
    for (int j = 0;; j++) {
        tf2x32(K0, K1, 0u, 1u, s0, s1);
        if (j == round) break;
        unsigned n0, n1; tf2x32(K0, K1, 0u, 0u, n0, n1);
        K0 = n0; K1 = n1;
    }
#else
    for (int j = 0;; j++) {
        unsigned a0, a1, b0, b1;
        tf2x32(K0, K1, 0u, 2u, a0, a1);
        tf2x32(K0, K1, 1u, 3u, b0, b1);
        s0 = a1; s1 = b1;
        if (j == round) break;
        K0 = a0; K1 = b0;
    }
#endif
}

// ---------------- kernels ----------------
__global__ void k_init_all() {
    int i = blockIdx.x * blockDim.x + threadIdx.x;
    if (i < NBUCK) g_cnt[i] = 0u;
    if (i < N_SEL) { g_ap[i] = 0u; g_an[i] = 0x7f800000u; }
}

__global__ void k_zero_cnt() {
    int i = blockIdx.x * blockDim.x + threadIdx.x;
    if (i < NBUCK) g_cnt[i] = 0u;
}

// fused: compute threefry keys AND build the 16-bit-MSB histogram in one pass
__global__ void k_keys_hist(const int* uuP, int round) {
    int i = blockIdx.x * blockDim.x + threadIdx.x;
    if (i >= N_TOT) return;
    unsigned uu = (unsigned)uuP[0];
    unsigned s0, s1; get_subkey(uu, round, s0, s1);
    unsigned o0, o1; tf2x32(s0, s1, 0u, (unsigned)i, o0, o1);
    g_key[i] = o0;
    atomicAdd(&g_cnt[o0 >> 16], 1u);
}

// ---- 3-stage grid-wide exclusive scan over 65536 counters ----
// stage A: 64 blocks x 1024 threads; per-block exclusive scan + block total
__global__ void k_scanA() {
    __shared__ unsigned s[1024];
    int t = threadIdx.x;
    int g = blockIdx.x * 1024 + t;
    unsigned v = g_cnt[g];
    s[t] = v;
    __syncthreads();
    for (int off = 1; off < 1024; off <<= 1) {
        unsigned u = (t >= off) ? s[t - off] : 0u;
        __syncthreads();
        s[t] += u;
        __syncthreads();
    }
    g_start[g] = s[t] - v;                // exclusive within block
    if (t == 1023) g_bsum[blockIdx.x] = s[t];
}

// stage B: exclusive scan of the 64 block totals
__global__ void k_scanB() {
    __shared__ unsigned s[64];
    int t = threadIdx.x;
    unsigned v = g_bsum[t];
    s[t] = v;
    __syncthreads();
    for (int off = 1; off < 64; off <<= 1) {
        unsigned u = (t >= off) ? s[t - off] : 0u;
        __syncthreads();
        s[t] += u;
        __syncthreads();
    }
    g_bsum[t] = s[t] - v;
}

// stage C: add block offsets, materialize g_start / g_cur
__global__ void k_scanC() {
    int g = blockIdx.x * 1024 + threadIdx.x;
    unsigned st = g_start[g] + g_bsum[blockIdx.x];
    g_start[g] = st;
    g_cur[g]   = st;
}

__global__ void k_scatter(int round) {
    int i = blockIdx.x * blockDim.x + threadIdx.x;
    if (i >= N_TOT) return;
    unsigned k = g_key[i];
    unsigned p = atomicAdd(&g_cur[k >> 16], 1u);
    if (round == 0) { g_keyB[p] = k; g_valB[p] = (unsigned)i;  g_idxB[p] = (unsigned)i; }
    else            { g_keyC[p] = k; g_valC[p] = g_valB[i];    g_idxC[p] = (unsigned)i; }
}

// restore exact stable order within each bucket: sort by (full key, original index)
__global__ void k_bsort(int round) {
    int b = blockIdx.x * blockDim.x + threadIdx.x;
    if (b >= NBUCK) return;
    unsigned n = g_cnt[b];
    if (n < 2u) return;
    unsigned s = g_start[b];
    unsigned* key = round ? g_keyC : g_keyB;
    unsigned* val = round ? g_valC : g_valB;
    unsigned* idx = round ? g_idxC : g_idxB;
    for (unsigned a = s + 1u; a < s + n; a++) {
        unsigned k = key[a], v = val[a], x = idx[a];
        int c = (int)a - 1;
        while (c >= (int)s && (key[c] > k || (key[c] == k && idx[c] > x))) {
            key[c + 1] = key[c]; val[c + 1] = val[c]; idx[c + 1] = idx[c];
            c--;
        }
        key[c + 1] = k; val[c + 1] = v; idx[c + 1] = x;
    }
}

// gather the first 5000 permuted rows + per-row squared norm + label
__global__ void k_gather(const float* __restrict__ X, const int* __restrict__ T) {
    int row = blockIdx.x;
    int t = threadIdx.x;           // 64 threads, one float4 each
    unsigned src = g_valC[row];
    float4 v = ((const float4*)(X + (size_t)src * DIMS))[t];
    ((float4*)(g_X + (size_t)row * DIMS))[t] = v;
    float ss = v.x * v.x + v.y * v.y + v.z * v.z + v.w * v.w;
    __shared__ float red[64];
    red[t] = ss;
    __syncthreads();
    if (t < 32) {
        float x = red[t] + red[t + 32];
        for (int o = 16; o > 0; o >>= 1) x += __shfl_down_sync(0xffffffffu, x, o);
        if (t == 0) { g_sq[row] = x; g_lab[row] = T[src]; }
    }
}

// fused  G = Xb*Xb^T  +  dist  +  batch-hard mining
__global__ void k_main() {
    extern __shared__ float sm[];
    float* As  = sm;                 // [256][64] k-major
    float* Bs  = sm + 256 * 64;
    float* sqA = sm + 2 * 256 * 64;
    float* sqB = sqA + 64;
    int*   labA = (int*)(sqB + 64);
    int*   labB = labA + 64;

    const int tid = threadIdx.x;
    const int tx = tid & 15, ty = tid >> 4;
    const int blk = blockIdx.z;
    const int r0 = blockIdx.x * 64;
    const int cStart = blockIdx.y * 500;
    const int cEnd = cStart + 500;
    const int nrows = min(64, BATCH - r0);
    const int rowBase = blk * BATCH + r0;

    for (int idx = tid; idx < 64 * 64; idx += 256) {
        int r = idx & 63, q = idx >> 6;
        float4 v = make_float4(0.f, 0.f, 0.f, 0.f);
        if (r < nrows) v = *(const float4*)&g_X[(size_t)(rowBase + r) * DIMS + q * 4];
        As[(q * 4 + 0) * 64 + r] = v.x;
        As[(q * 4 + 1) * 64 + r] = v.y;
        As[(q * 4 + 2) * 64 + r] = v.z;
        As[(q * 4 + 3) * 64 + r] = v.w;
    }
    if (tid < 64) {
        sqA[tid]  = (tid < nrows) ? g_sq[rowBase + tid] : 0.f;
        labA[tid] = (tid < nrows) ? g_lab[rowBase + tid] : -1;
    }

    float rmax[4] = {0.f, 0.f, 0.f, 0.f};
    float rmin[4];
    rmin[0] = rmin[1] = rmin[2] = rmin[3] = __uint_as_float(0x7f800000u);

    for (int c0 = cStart; c0 < cEnd; c0 += 64) {
        const int ncols = min(64, cEnd - c0);
        const int colBase = blk * BATCH + c0;
        __syncthreads();
        for (int idx = tid; idx < 64 * 64; idx += 256) {
            int r = idx & 63, q = idx >> 6;
            float4 v = make_float4(0.f, 0.f, 0.f, 0.f);
            if (r < ncols) v = *(const float4*)&g_X[(size_t)(colBase + r) * DIMS + q * 4];
            Bs[(q * 4 + 0) * 64 + r] = v.x;
            Bs[(q * 4 + 1) * 64 + r] = v.y;
            Bs[(q * 4 + 2) * 64 + r] = v.z;
            Bs[(q * 4 + 3) * 64 + r] = v.w;
        }
        if (tid < 64) {
            sqB[tid]  = (tid < ncols) ? g_sq[colBase + tid] : 0.f;
            labB[tid] = (tid < ncols) ? g_lab[colBase + tid] : 0x7fffffff;
        }
        __syncthreads();

        float acc[4][4];
#pragma unroll
        for (int i = 0; i < 4; i++)
#pragma unroll
            for (int j = 0; j < 4; j++) acc[i][j] = 0.f;

#pragma unroll 8
        for (int k = 0; k < DIMS; k++) {
            float4 a = *(const float4*)&As[k * 64 + ty * 4];
            float4 b = *(const float4*)&Bs[k * 64 + tx * 4];
            acc[0][0] += a.x * b.x; acc[0][1] += a.x * b.y; acc[0][2] += a.x * b.z; acc[0][3] += a.x * b.w;
            acc[1][0] += a.y * b.x; acc[1][1] += a.y * b.y; acc[1][2] += a.y * b.z; acc[1][3] += a.y * b.w;
            acc[2][0] += a.z * b.x; acc[2][1] += a.z * b.y; acc[2][2] += a.z * b.z; acc[2][3] += a.z * b.w;
            acc[3][0] += a.w * b.x; acc[3][1] += a.w * b.y; acc[3][2] += a.w * b.z; acc[3][3] += a.w * b.w;
        }

#pragma unroll
        for (int i = 0; i < 4; i++) {
            int gr = ty * 4 + i;
            float sqi = sqA[gr];
            int   li  = labA[gr];
#pragma unroll
            for (int j = 0; j < 4; j++) {
                int gc = tx * 4 + j;
                if (gr < nrows && gc < ncols) {
                    float d2 = sqi + sqB[gc] - 2.f * acc[i][j];
                    float dist = sqrtf(fmaxf(d2, 1e-12f));
                    if (li == labB[gc]) rmax[i] = fmaxf(rmax[i], dist);
                    else                rmin[i] = fminf(rmin[i], dist);
                }
            }
        }
    }

#pragma unroll
    for (int i = 0; i < 4; i++) {
        int gr = ty * 4 + i;
        if (gr < nrows) {
            int row = rowBase + gr;
            atomicMax(&g_ap[row], __float_as_uint(rmax[i]));
            atomicMin(&g_an[row], __float_as_uint(rmin[i]));
        }
    }
}

__global__ void k_reduce(float* __restrict__ out) {
    __shared__ float s[1024];
    int t = threadIdx.x;
    float acc = 0.f;
    for (int i = t; i < N_SEL; i += 1024) {
        float ap = __uint_as_float(g_ap[i]);
        float an = __uint_as_float(g_an[i]);
        acc += fmaxf(ap - an + 0.5f, 0.f);
    }
    s[t] = acc;
    __syncthreads();
    for (int off = 512; off > 0; off >>= 1) {
        if (t < off) s[t] += s[t + off];
        __syncthreads();
    }
    if (t == 0) out[0] = s[0] * (1.0f / (float)BATCH);
}

// ---------------- launch ----------------
extern "C" void kernel_launch(void* const* d_in, const int* in_sizes, int n_in,
                              void* d_out, int out_size) {
    const float* X  = (const float*)d_in[0];
    const int*   T  = (const int*)d_in[1];
    const int*   UU = (const int*)d_in[2];
    float* out = (float*)d_out;
    (void)in_sizes; (void)n_in; (void)out_size;

    const int TB = 256;
    const int gN = (N_TOT + TB - 1) / TB;
    const int gB = NBUCK / TB;
    const int SMEM_MAIN = (2 * 256 * 64 + 2 * 64) * (int)sizeof(float) + 2 * 64 * (int)sizeof(int);

    cudaFuncSetAttribute(k_main, cudaFuncAttributeMaxDynamicSharedMemorySize, SMEM_MAIN);

    k_init_all<<<gB, TB>>>();

    // shuffle round 1
    k_keys_hist<<<gN, TB>>>(UU, 0);
    k_scanA<<<64, 1024>>>();
    k_scanB<<<1, 64>>>();
    k_scanC<<<64, 1024>>>();
    k_scatter<<<gN, TB>>>(0);
    k_bsort<<<gB, TB>>>(0);

    // shuffle round 2
    k_zero_cnt<<<gB, TB>>>();
    k_keys_hist<<<gN, TB>>>(UU, 1);
    k_scanA<<<64, 1024>>>();
    k_scanB<<<1, 64>>>();
    k_scanC<<<64, 1024>>>();
    k_scatter<<<gN, TB>>>(1);
    k_bsort<<<gB, TB>>>(1);

    // gather + fused gemm/mining + reduce
    k_gather<<<N_SEL, 64>>>(X, T);
    k_main<<<dim3(16, 2, NB), 256, SMEM_MAIN>>>();
    k_reduce<<<1, 1024>>>(out);
}